// round 12
// baseline (speedup 1.0000x reference)
#include <cuda_runtime.h>
#include <cuda_fp16.h>

#define TPB 256
#define NBLOCKS 1216           // 152 SMs * 8 (persistent; stealing makes residency moot)
#define MAX_LAYERS 64
#define CHUNK 32               // float4 per warp-chunk: 1 f4/lane = 2 pts/thread

__device__ unsigned g_chunk_ctr;

__global__ void reset_ctr_kernel() { g_chunk_ctr = 0u; }

__device__ __forceinline__ __half2 tanh_h2(__half2 x) {
    __half2 y;
    asm("tanh.approx.f16x2 %0, %1;"
        : "=r"(*reinterpret_cast<unsigned int*>(&y))
        : "r"(*reinterpret_cast<const unsigned int*>(&x)));
    return y;
}

__device__ __forceinline__ __half2 u2h(unsigned u) {
    __half2 h; *reinterpret_cast<unsigned*>(&h) = u; return h;
}

__device__ __forceinline__ float2 fin_norm(float x0, float x1,
                                           float f00, float f01, float f10, float f11) {
    float o0 = fmaf(f00, x0, f01 * x1);
    float o1 = fmaf(f10, x0, f11 * x1);
    float s  = fmaf(o0, o0, o1 * o1);
    float inv = rsqrtf(s);
    inv = inv * fmaf(-0.5f * s * inv, inv, 1.5f);    // one Newton step
    if (s < 1e-24f) inv = 1e12f;                     // eps=1e-12 clamp
    return make_float2(o0 * inv, o1 * inv);
}

// Pure-MUFU half2 path (proven R3 inner loop) + persistent warp-level work
// stealing: warps pull 32-float4 chunks from a global counter, so the wave-
// quantization tail (~3.9% in R3's 6.74-wave launch) collapses to <1 chunk.
// z-form: z = 2x for l>=1 (0.5 folded into W); final normalize is scale-invariant.
__global__ __launch_bounds__(TPB, 6) void nignet_kernel(
    const float4* __restrict__ pts,   // (N,2): one float4 = 2 points
    const float*  __restrict__ Ws,    // (L,2,2)
    const float*  __restrict__ bs,    // (L,2)
    const float*  __restrict__ fW,    // (2,2)
    float4* __restrict__ out,
    int nf4, int nchunks, int layers)
{
    __shared__ __align__(16) uint4 sW [MAX_LAYERS];  // w00,w01,w10,w11 (half2 dup'd)
    __shared__ __align__(8)  uint2 sWb[MAX_LAYERS];  // b0,b1 (half2 dup'd)
    __shared__ float sf[4];

    const int tid = threadIdx.x;
    if (tid < layers) {
        const float scl = (tid == 0) ? 1.0f : 0.5f;  // fold residual *0.5 into W
        float4 w = ((const float4*)Ws)[tid];
        float2 b = ((const float2*)bs)[tid];
        __half2 h;
        uint4 ua;
        h = __float2half2_rn(w.x * scl); ua.x = *reinterpret_cast<unsigned*>(&h);
        h = __float2half2_rn(w.y * scl); ua.y = *reinterpret_cast<unsigned*>(&h);
        h = __float2half2_rn(w.z * scl); ua.z = *reinterpret_cast<unsigned*>(&h);
        h = __float2half2_rn(w.w * scl); ua.w = *reinterpret_cast<unsigned*>(&h);
        sW[tid] = ua;
        uint2 ub;
        h = __float2half2_rn(b.x); ub.x = *reinterpret_cast<unsigned*>(&h);
        h = __float2half2_rn(b.y); ub.y = *reinterpret_cast<unsigned*>(&h);
        sWb[tid] = ub;
    }
    if (tid < 4) sf[tid] = fW[tid];
    __syncthreads();

    const int lane = tid & 31;
    const float f00 = sf[0], f01 = sf[1], f10 = sf[2], f11 = sf[3];
    const float4 zero4 = make_float4(0.f, 0.f, 0.f, 0.f);

    for (;;) {
        unsigned c = 0;
        if (lane == 0) c = atomicAdd(&g_chunk_ctr, 1u);
        c = __shfl_sync(0xFFFFFFFFu, c, 0);
        if (c >= (unsigned)nchunks) break;

        const int idx = (int)c * CHUNK + lane;
        const bool valid = idx < nf4;
        float4 v = valid ? pts[idx] : zero4;          // point A=(x,y), B=(z,w)

        __half2 X0 = __floats2half2_rn(v.x, v.z);     // (x0_A, x0_B)
        __half2 X1 = __floats2half2_rn(v.y, v.w);     // (x1_A, x1_B)

        #pragma unroll 4
        for (int l = 0; l < layers; ++l) {
            const uint4 ua = sW[l];                   // LDS.128
            const uint2 ub = sWb[l];                  // LDS.64
            const __half2 w00 = u2h(ua.x), w01 = u2h(ua.y);
            const __half2 w10 = u2h(ua.z), w11 = u2h(ua.w);
            const __half2 b0  = u2h(ub.x), b1  = u2h(ub.y);
            __half2 y0 = __hfma2(w00, X0, __hfma2(w01, X1, b0));
            __half2 y1 = __hfma2(w10, X0, __hfma2(w11, X1, b1));
            __half2 t0 = tanh_h2(y0);
            __half2 t1 = tanh_h2(y1);
            X0 = __hadd2(t0, y0);                     // z' = tanh(y) + y
            X1 = __hadd2(t1, y1);
        }

        // Epilogue (fp32): final matvec + L2 row-normalize.
        const float2 a0 = __half22float2(X0);         // (x0_A, x0_B)
        const float2 a1 = __half22float2(X1);         // (x1_A, x1_B)
        float2 rA = fin_norm(a0.x, a1.x, f00, f01, f10, f11);
        float2 rB = fin_norm(a0.y, a1.y, f00, f01, f10, f11);
        if (valid) out[idx] = make_float4(rA.x, rA.y, rB.x, rB.y);
    }
}

extern "C" void kernel_launch(void* const* d_in, const int* in_sizes, int n_in,
                              void* d_out, int out_size) {
    // metadata order: T(1), closed_manifold(N*2), Ws(L*4), bs(L*2), final_W(4)
    const float* pts = (const float*)d_in[1];
    const float* Ws  = (const float*)d_in[2];
    const float* bs  = (const float*)d_in[3];
    const float* fW  = (const float*)d_in[4];
    float* out = (float*)d_out;

    const int n       = in_sizes[1] / 2;   // number of points
    const int layers  = in_sizes[2] / 4;   // 64
    const int nf4     = n / 2;             // 2 points per float4
    const int nchunks = (nf4 + CHUNK - 1) / CHUNK;

    reset_ctr_kernel<<<1, 1>>>();
    nignet_kernel<<<NBLOCKS, TPB>>>(
        (const float4*)pts, Ws, bs, fW, (float4*)out, nf4, nchunks, layers);
}

// round 13
// speedup vs baseline: 1.0664x; 1.0664x over previous
#include <cuda_runtime.h>
#include <cuda_fp16.h>

#define TPB 256
#define MAX_LAYERS 64

__device__ __forceinline__ __half2 tanh_h2(__half2 x) {
    __half2 y;
    asm("tanh.approx.f16x2 %0, %1;"
        : "=r"(*reinterpret_cast<unsigned int*>(&y))
        : "r"(*reinterpret_cast<const unsigned int*>(&x)));
    return y;
}

// 2 points per thread, SoA-packed in half2:
//   X0 = (x0_A, x0_B), X1 = (x1_A, x1_B)
// Layer l (z-form, z = 2x for l>=1; final normalize is scale-invariant):
//   y0 = w00*X0 + w01*X1 + b0   (w duplicated into both halves)
//   y1 = w10*X0 + w11*X1 + b1
//   X0' = tanh(y0) + y0 ; X1' = tanh(y1) + y1
// This sits on the MUFU roofline: 0.5 MUFU-cyc per point-layer.
__global__ __launch_bounds__(TPB, 8) void nignet_kernel(
    const float4* __restrict__ pts,   // (N,2): one float4 = 2 points
    const float*  __restrict__ Ws,    // (L,2,2)
    const float*  __restrict__ bs,    // (L,2)
    const float*  __restrict__ fW,    // (2,2)
    float4* __restrict__ out,
    int nf4,
    int layers)
{
    __shared__ __align__(16) __half2 sw[MAX_LAYERS][4];  // w00,w01,w10,w11 dup'd
    __shared__ __align__(8)  __half2 sb[MAX_LAYERS][2];  // b0,b1 dup'd
    __shared__ float sf[4];

    const int tid = threadIdx.x;
    if (tid < layers) {
        const float s = (tid == 0) ? 1.0f : 0.5f;   // fold the residual *0.5 into W
        float4 w = ((const float4*)Ws)[tid];
        sw[tid][0] = __float2half2_rn(w.x * s);
        sw[tid][1] = __float2half2_rn(w.y * s);
        sw[tid][2] = __float2half2_rn(w.z * s);
        sw[tid][3] = __float2half2_rn(w.w * s);
        float2 b = ((const float2*)bs)[tid];
        sb[tid][0] = __float2half2_rn(b.x);
        sb[tid][1] = __float2half2_rn(b.y);
    }
    if (tid < 4) sf[tid] = fW[tid];
    __syncthreads();

    const int idx = blockIdx.x * TPB + tid;
    if (idx >= nf4) return;

    float4 v = pts[idx];                       // point A = (v.x,v.y), B = (v.z,v.w)
    __half2 X0 = __floats2half2_rn(v.x, v.z);  // (x0_A, x0_B)
    __half2 X1 = __floats2half2_rn(v.y, v.w);  // (x1_A, x1_B)

    #pragma unroll 4
    for (int l = 0; l < layers; ++l) {
        const __half2 w00 = sw[l][0], w01 = sw[l][1];
        const __half2 w10 = sw[l][2], w11 = sw[l][3];
        const __half2 b0  = sb[l][0], b1  = sb[l][1];
        __half2 y0 = __hfma2(w00, X0, __hfma2(w01, X1, b0));
        __half2 y1 = __hfma2(w10, X0, __hfma2(w11, X1, b1));
        __half2 t0 = tanh_h2(y0);
        __half2 t1 = tanh_h2(y1);
        X0 = __hadd2(t0, y0);
        X1 = __hadd2(t1, y1);
    }

    // Epilogue in fp32: final matvec + L2 row-normalize.
    const float f00 = sf[0], f01 = sf[1], f10 = sf[2], f11 = sf[3];
    const float2 a0 = __half22float2(X0);   // (x0_A, x0_B)
    const float2 a1 = __half22float2(X1);   // (x1_A, x1_B)

    float4 r;
    {
        float o0 = fmaf(f00, a0.x, f01 * a1.x);
        float o1 = fmaf(f10, a0.x, f11 * a1.x);
        float s  = fmaf(o0, o0, o1 * o1);
        float inv = rsqrtf(s);
        inv = inv * fmaf(-0.5f * s * inv, inv, 1.5f);   // one Newton step
        if (s < 1e-24f) inv = 1e12f;                    // eps=1e-12 clamp
        r.x = o0 * inv;
        r.y = o1 * inv;
    }
    {
        float o0 = fmaf(f00, a0.y, f01 * a1.y);
        float o1 = fmaf(f10, a0.y, f11 * a1.y);
        float s  = fmaf(o0, o0, o1 * o1);
        float inv = rsqrtf(s);
        inv = inv * fmaf(-0.5f * s * inv, inv, 1.5f);
        if (s < 1e-24f) inv = 1e12f;
        r.z = o0 * inv;
        r.w = o1 * inv;
    }
    out[idx] = r;
}

extern "C" void kernel_launch(void* const* d_in, const int* in_sizes, int n_in,
                              void* d_out, int out_size) {
    // metadata order: T(1), closed_manifold(N*2), Ws(L*4), bs(L*2), final_W(4)
    const float* pts = (const float*)d_in[1];
    const float* Ws  = (const float*)d_in[2];
    const float* bs  = (const float*)d_in[3];
    const float* fW  = (const float*)d_in[4];
    float* out = (float*)d_out;

    const int n      = in_sizes[1] / 2;   // number of points
    const int layers = in_sizes[2] / 4;   // 64
    const int nf4    = n / 2;             // 2 points per float4

    const int grid = (nf4 + TPB - 1) / TPB;
    nignet_kernel<<<grid, TPB>>>(
        (const float4*)pts, Ws, bs, fW, (float4*)out, nf4, layers);
}

// round 14
// speedup vs baseline: 1.0672x; 1.0008x over previous
#include <cuda_runtime.h>
#include <cuda_fp16.h>

#define TPB 256
#define MAX_LAYERS 64

__device__ __forceinline__ __half2 tanh_h2(__half2 x) {
    __half2 y;
    asm("tanh.approx.f16x2 %0, %1;"
        : "=r"(*reinterpret_cast<unsigned int*>(&y))
        : "r"(*reinterpret_cast<const unsigned int*>(&x)));
    return y;
}

// 2 points per thread, SoA-packed in half2:
//   X0 = (x0_A, x0_B), X1 = (x1_A, x1_B)
// Layer l (z-form, z = 2x for l>=1; final normalize is scale-invariant):
//   y0 = w00*X0 + w01*X1 + b0   (w duplicated into both halves)
//   y1 = w10*X0 + w11*X1 + b1
//   X0' = tanh(y0) + y0 ; X1' = tanh(y1) + y1
// MUFU roofline: 2 tanh.f16x2 x 2 micro-ops x rt8 = 32 SMSP-cyc per warp-layer;
// 65536 warps x 64 layers x 32 / 608 SMSPs = 220K cyc ~= 115 us @ ~1.91 GHz.
__global__ __launch_bounds__(TPB, 8) void nignet_kernel(
    const float4* __restrict__ pts,   // (N,2): one float4 = 2 points
    const float*  __restrict__ Ws,    // (L,2,2)
    const float*  __restrict__ bs,    // (L,2)
    const float*  __restrict__ fW,    // (2,2)
    float4* __restrict__ out,
    int nf4,
    int layers)
{
    __shared__ __align__(16) __half2 sw[MAX_LAYERS][4];  // w00,w01,w10,w11 dup'd
    __shared__ __align__(8)  __half2 sb[MAX_LAYERS][2];  // b0,b1 dup'd
    __shared__ float sf[4];

    const int tid = threadIdx.x;
    if (tid < layers) {
        const float s = (tid == 0) ? 1.0f : 0.5f;   // fold the residual *0.5 into W
        float4 w = ((const float4*)Ws)[tid];
        sw[tid][0] = __float2half2_rn(w.x * s);
        sw[tid][1] = __float2half2_rn(w.y * s);
        sw[tid][2] = __float2half2_rn(w.z * s);
        sw[tid][3] = __float2half2_rn(w.w * s);
        float2 b = ((const float2*)bs)[tid];
        sb[tid][0] = __float2half2_rn(b.x);
        sb[tid][1] = __float2half2_rn(b.y);
    }
    if (tid < 4) sf[tid] = fW[tid];
    __syncthreads();

    const int idx = blockIdx.x * TPB + tid;
    if (idx >= nf4) return;

    float4 v = pts[idx];                       // point A = (v.x,v.y), B = (v.z,v.w)
    __half2 X0 = __floats2half2_rn(v.x, v.z);  // (x0_A, x0_B)
    __half2 X1 = __floats2half2_rn(v.y, v.w);  // (x1_A, x1_B)

    #pragma unroll 4
    for (int l = 0; l < layers; ++l) {
        const __half2 w00 = sw[l][0], w01 = sw[l][1];
        const __half2 w10 = sw[l][2], w11 = sw[l][3];
        const __half2 b0  = sb[l][0], b1  = sb[l][1];
        __half2 y0 = __hfma2(w00, X0, __hfma2(w01, X1, b0));
        __half2 y1 = __hfma2(w10, X0, __hfma2(w11, X1, b1));
        __half2 t0 = tanh_h2(y0);
        __half2 t1 = tanh_h2(y1);
        X0 = __hadd2(t0, y0);
        X1 = __hadd2(t1, y1);
    }

    // Epilogue in fp32: final matvec + L2 row-normalize.
    const float f00 = sf[0], f01 = sf[1], f10 = sf[2], f11 = sf[3];
    const float2 a0 = __half22float2(X0);   // (x0_A, x0_B)
    const float2 a1 = __half22float2(X1);   // (x1_A, x1_B)

    float4 r;
    {
        float o0 = fmaf(f00, a0.x, f01 * a1.x);
        float o1 = fmaf(f10, a0.x, f11 * a1.x);
        float s  = fmaf(o0, o0, o1 * o1);
        float inv = rsqrtf(s);
        inv = inv * fmaf(-0.5f * s * inv, inv, 1.5f);   // one Newton step
        if (s < 1e-24f) inv = 1e12f;                    // eps=1e-12 clamp
        r.x = o0 * inv;
        r.y = o1 * inv;
    }
    {
        float o0 = fmaf(f00, a0.y, f01 * a1.y);
        float o1 = fmaf(f10, a0.y, f11 * a1.y);
        float s  = fmaf(o0, o0, o1 * o1);
        float inv = rsqrtf(s);
        inv = inv * fmaf(-0.5f * s * inv, inv, 1.5f);
        if (s < 1e-24f) inv = 1e12f;
        r.z = o0 * inv;
        r.w = o1 * inv;
    }
    out[idx] = r;
}

extern "C" void kernel_launch(void* const* d_in, const int* in_sizes, int n_in,
                              void* d_out, int out_size) {
    // metadata order: T(1), closed_manifold(N*2), Ws(L*4), bs(L*2), final_W(4)
    const float* pts = (const float*)d_in[1];
    const float* Ws  = (const float*)d_in[2];
    const float* bs  = (const float*)d_in[3];
    const float* fW  = (const float*)d_in[4];
    float* out = (float*)d_out;

    const int n      = in_sizes[1] / 2;   // number of points
    const int layers = in_sizes[2] / 4;   // 64
    const int nf4    = n / 2;             // 2 points per float4

    const int grid = (nf4 + TPB - 1) / TPB;
    nignet_kernel<<<grid, TPB>>>(
        (const float4*)pts, Ws, bs, fW, (float4*)out, nf4, layers);
}